// round 1
// baseline (speedup 1.0000x reference)
#include <cuda_runtime.h>

#define POP    4096
#define SPLITK 32
#define KCHUNK (POP / SPLITK)   // 128
#define BK     8
#define BM     128
#define BN     128
#define KSTEPS (KCHUNK / BK)    // 16

// Scratch (allocation-free rule: __device__ globals)
__device__ __align__(16) float g_M1[POP * 256];              // 4 MB  (w_p * A_p)
__device__ __align__(16) float g_M2[POP * 256];              // 4 MB  (B_p)
__device__ __align__(16) float g_part[SPLITK * 256 * 256];   // 8 MB  split-K partials

typedef unsigned long long u64;

__device__ __forceinline__ u64 pack2(float x) {
    u64 r; asm("mov.b64 %0, {%1, %1};" : "=l"(r) : "f"(x)); return r;
}
__device__ __forceinline__ void ffma2(u64& d, u64 a, u64 b) {
    asm("fma.rn.f32x2 %0, %1, %2, %0;" : "+l"(d) : "l"(a), "l"(b));
}

// ---------------------------------------------------------------------------
// Kernel 1: build M1 = w_p * kron(B0..B3) flattened, M2 = kron(B4..B7).
// Row bit of codon c is bit (3-c) of the half-index (codon 0 = MSB).
// ---------------------------------------------------------------------------
__global__ void build_kernel(const float* __restrict__ w,
                             const int*   __restrict__ idx,
                             const float* __restrict__ bbg) {
    __shared__ float bb[144];
    __shared__ int   id[8];
    __shared__ float wp;
    const int p = blockIdx.x;
    const int t = threadIdx.x;
    if (t < 144) bb[t] = bbg[t];
    if (t < 8)   id[t] = idx[p * 8 + t];
    if (t == 255) wp = w[p];
    __syncthreads();
    const int r = t >> 4, c = t & 15;
    float vA = bb[id[0] * 4 + ((r >> 3) & 1) * 2 + ((c >> 3) & 1)]
             * bb[id[1] * 4 + ((r >> 2) & 1) * 2 + ((c >> 2) & 1)]
             * bb[id[2] * 4 + ((r >> 1) & 1) * 2 + ((c >> 1) & 1)]
             * bb[id[3] * 4 + ( r       & 1) * 2 + ( c       & 1)];
    float vB = bb[id[4] * 4 + ((r >> 3) & 1) * 2 + ((c >> 3) & 1)]
             * bb[id[5] * 4 + ((r >> 2) & 1) * 2 + ((c >> 2) & 1)]
             * bb[id[6] * 4 + ((r >> 1) & 1) * 2 + ((c >> 1) & 1)]
             * bb[id[7] * 4 + ( r       & 1) * 2 + ( c       & 1)];
    g_M1[p * 256 + t] = wp * vA;
    g_M2[p * 256 + t] = vB;
}

// ---------------------------------------------------------------------------
// Kernel 2: split-K GEMM  G[a,b] = sum_k M1[k,a] * M2[k,b]
// 128x128 tile, 256 threads, 8x8 micro-tile per thread, FFMA2 (f32x2).
// Grid: (2, 2, SPLITK). Each z-slice writes its own partial buffer.
// ---------------------------------------------------------------------------
__global__ void __launch_bounds__(256, 1) gemm_kernel() {
    __shared__ float As[BK][BM];
    __shared__ float Bs[BK][BN];

    const int tid = threadIdx.x;
    const int a0 = blockIdx.x * BM;
    const int b0 = blockIdx.y * BN;
    const int kbase = blockIdx.z * KCHUNK;

    const int lr = tid >> 5;          // 0..7  (k row within step)
    const int lc = (tid & 31) * 4;    // 0..124 (col, float4)

    const float4* pA = (const float4*)&g_M1[(kbase + lr) * 256 + a0 + lc];
    const float4* pB = (const float4*)&g_M2[(kbase + lr) * 256 + b0 + lc];
    float4 fa = *pA;
    float4 fb = *pB;

    const int ty = tid >> 4;          // 0..15 (m group of 8 rows)
    const int tx = tid & 15;          // 0..15 (n group of 8 cols)

    u64 acc[8][4];
    #pragma unroll
    for (int i = 0; i < 8; i++)
        #pragma unroll
        for (int j = 0; j < 4; j++) acc[i][j] = 0ull;

    for (int kt = 0; kt < KSTEPS; kt++) {
        *(float4*)&As[lr][lc] = fa;
        *(float4*)&Bs[lr][lc] = fb;
        __syncthreads();
        if (kt + 1 < KSTEPS) {        // prefetch next tile (hides gmem latency)
            fa = pA[(kt + 1) * 512];  // 512 float4 = BK rows * 256 floats
            fb = pB[(kt + 1) * 512];
        }
        #pragma unroll
        for (int kk = 0; kk < BK; kk++) {
            float4 aLo = *(const float4*)&As[kk][ty * 8];
            float4 aHi = *(const float4*)&As[kk][ty * 8 + 4];
            ulonglong2 bLo = *(const ulonglong2*)&Bs[kk][tx * 8];
            ulonglong2 bHi = *(const ulonglong2*)&Bs[kk][tx * 8 + 4];
            u64 av[8] = {pack2(aLo.x), pack2(aLo.y), pack2(aLo.z), pack2(aLo.w),
                         pack2(aHi.x), pack2(aHi.y), pack2(aHi.z), pack2(aHi.w)};
            #pragma unroll
            for (int i = 0; i < 8; i++) {
                ffma2(acc[i][0], av[i], bLo.x);
                ffma2(acc[i][1], av[i], bLo.y);
                ffma2(acc[i][2], av[i], bHi.x);
                ffma2(acc[i][3], av[i], bHi.y);
            }
        }
        __syncthreads();
    }

    float* part = &g_part[blockIdx.z * 65536];
    #pragma unroll
    for (int i = 0; i < 8; i++) {
        const int a = a0 + ty * 8 + i;
        float* dst = &part[a * 256 + b0 + tx * 8];
        *(ulonglong2*)(dst)     = make_ulonglong2(acc[i][0], acc[i][1]);
        *(ulonglong2*)(dst + 4) = make_ulonglong2(acc[i][2], acc[i][3]);
    }
}

// ---------------------------------------------------------------------------
// Kernel 3: sum split-K partials and scatter with the Kronecker index
// permutation: out[(iH*16+iL)*256 + (jH*16+jL)] = G[iH*16+jH, iL*16+jL]
// ---------------------------------------------------------------------------
__global__ void reduce_kernel(float* __restrict__ out) {
    const int t = blockIdx.x * 256 + threadIdx.x;   // 0..65535 = a*256 + b
    float s = 0.f;
    #pragma unroll
    for (int k = 0; k < SPLITK; k++) s += g_part[k * 65536 + t];
    const int a = t >> 8, b = t & 255;
    const int iH = a >> 4, jH = a & 15;
    const int iL = b >> 4, jL = b & 15;
    out[(iH * 16 + iL) * 256 + (jH * 16 + jL)] = s;
}

extern "C" void kernel_launch(void* const* d_in, const int* in_sizes, int n_in,
                              void* d_out, int out_size) {
    const float* w   = (const float*)d_in[0];   // weights   [4096] f32
    const int*   idx = (const int*)  d_in[1];   // indices   [4096,8] i32
    const float* bb  = (const float*)d_in[2];   // blocks    [36,2,2] f32

    build_kernel<<<POP, 256>>>(w, idx, bb);
    gemm_kernel<<<dim3(2, 2, SPLITK), 256>>>();
    reduce_kernel<<<256, 256>>>((float*)d_out);
}